// round 8
// baseline (speedup 1.0000x reference)
#include <cuda_runtime.h>
#include <cstdint>

// Round 7: sector-granular access — each thread reads 2 adjacent float4s
// (32B = one full sector) per stream; warp covers 1KB contiguous per stream
// per step. Same MLP (4 LDG.128/thread), same occ (6 CTAs/SM) as best config.
// Tests whether DRAM page locality lifts the 6.47 TB/s ceiling.
// Predict DRAM 81.7 -> 84-86% (or flat if page locality is not a lever).

__global__ void rw_zero_kernel(float* out) {
    out[0] = 0.0f;
}

__device__ __forceinline__ float bce_w(float x, int h, int mid, float t) {
    float ax  = fabsf(x);
    float e   = __expf(-ax);
    float sp  = __logf(1.0f + e);             // log1p(exp(-|x|)), e in (0,1]
    float bce = fmaxf(x, 0.0f) - x * t + sp;
    return (h >= mid) ? (bce + bce) : bce;    // weight 2 or 1
}

__global__ __launch_bounds__(256, 6)
void rw_loss_kernel(const float4* __restrict__ x4,
                    const int4*  __restrict__ h4,
                    const int*   __restrict__ target_p,
                    const int*   __restrict__ H_p,
                    float*       __restrict__ out,
                    int nvec8, float inv_n) {
    const float t   = (float)(*target_p);
    const int   mid = (*H_p) >> 1;

    const int stride = gridDim.x * blockDim.x;
    float acc = 0.0f;

    // Each j handles 8 elements: float4 pair at 2j, 2j+1 (32B contiguous per
    // thread per stream). 4 independent LDG.128 batched at loop front.
    for (int j = blockIdx.x * blockDim.x + threadIdx.x; j < nvec8; j += stride) {
        const int base = 2 * j;
        float4 a0 = __ldcs(&x4[base]);
        float4 a1 = __ldcs(&x4[base + 1]);
        int4   b0 = __ldcs(&h4[base]);
        int4   b1 = __ldcs(&h4[base + 1]);

        acc += bce_w(a0.x, b0.x, mid, t);
        acc += bce_w(a0.y, b0.y, mid, t);
        acc += bce_w(a0.z, b0.z, mid, t);
        acc += bce_w(a0.w, b0.w, mid, t);
        acc += bce_w(a1.x, b1.x, mid, t);
        acc += bce_w(a1.y, b1.y, mid, t);
        acc += bce_w(a1.z, b1.z, mid, t);
        acc += bce_w(a1.w, b1.w, mid, t);
    }

    // warp reduction
    #pragma unroll
    for (int off = 16; off > 0; off >>= 1)
        acc += __shfl_xor_sync(0xFFFFFFFF, acc, off);

    __shared__ float warp_sums[8];
    const int lane = threadIdx.x & 31;
    const int wid  = threadIdx.x >> 5;
    if (lane == 0) warp_sums[wid] = acc;
    __syncthreads();

    if (wid == 0) {
        float v = (lane < 8) ? warp_sums[lane] : 0.0f;
        #pragma unroll
        for (int off = 4; off > 0; off >>= 1)
            v += __shfl_xor_sync(0xFFFFFFFF, v, off);
        if (lane == 0)
            atomicAdd(out, v * inv_n);
    }
}

extern "C" void kernel_launch(void* const* d_in, const int* in_sizes, int n_in,
                              void* d_out, int out_size) {
    const float* x      = (const float*)d_in[0];   // logits, N fp32
    const int*   target = (const int*)d_in[1];     // scalar int
    const int*   hidx   = (const int*)d_in[2];     // height_indices, N int32
    const int*   Hp     = (const int*)d_in[3];     // scalar int
    float* out = (float*)d_out;

    const int n = in_sizes[0];
    const int nvec8 = n / 8;   // N divisible by 8
    const float inv_n = 1.0f / (float)n;

    rw_zero_kernel<<<1, 1>>>(out);

    const int threads = 256;
    const int blocks  = 888;  // 148 SMs * 6
    rw_loss_kernel<<<blocks, threads>>>(
        (const float4*)x, (const int4*)hidx, target, Hp, out, nvec8, inv_n);
}

// round 9
// speedup vs baseline: 1.0007x; 1.0007x over previous
#include <cuda_runtime.h>
#include <cstdint>

// Round 8: R7's contiguous-sector mainloop (83.6% DRAM) + cheap fusion:
// one global atomicAdd accumulator per block, last-arriving block finalizes.
// Removes the zero-kernel launch. Predict dur 43.78 -> ~42.5us.

__device__ float    g_accum = 0.0f;
__device__ unsigned g_done_count = 0;

__global__ void rw_zero_kernel(float* out) { out[0] = 0.0f; }  // unused, kept harmless

__device__ __forceinline__ float bce_w(float x, int h, int mid, float t) {
    float ax  = fabsf(x);
    float e   = __expf(-ax);
    float sp  = __logf(1.0f + e);             // log1p(exp(-|x|)), e in (0,1]
    float bce = fmaxf(x, 0.0f) - x * t + sp;
    return (h >= mid) ? (bce + bce) : bce;    // weight 2 or 1
}

__global__ __launch_bounds__(256, 6)
void rw_loss_kernel(const float4* __restrict__ x4,
                    const int4*  __restrict__ h4,
                    const int*   __restrict__ target_p,
                    const int*   __restrict__ H_p,
                    float*       __restrict__ out,
                    int nvec8, float inv_n) {
    const float t   = (float)(*target_p);
    const int   mid = (*H_p) >> 1;

    const int stride = gridDim.x * blockDim.x;
    float acc = 0.0f;

    // Each j handles 8 elements: float4 pair at 2j, 2j+1 (32B contiguous per
    // thread per stream). 4 independent LDG.128 batched at loop front.
    for (int j = blockIdx.x * blockDim.x + threadIdx.x; j < nvec8; j += stride) {
        const int base = 2 * j;
        float4 a0 = __ldcs(&x4[base]);
        float4 a1 = __ldcs(&x4[base + 1]);
        int4   b0 = __ldcs(&h4[base]);
        int4   b1 = __ldcs(&h4[base + 1]);

        acc += bce_w(a0.x, b0.x, mid, t);
        acc += bce_w(a0.y, b0.y, mid, t);
        acc += bce_w(a0.z, b0.z, mid, t);
        acc += bce_w(a0.w, b0.w, mid, t);
        acc += bce_w(a1.x, b1.x, mid, t);
        acc += bce_w(a1.y, b1.y, mid, t);
        acc += bce_w(a1.z, b1.z, mid, t);
        acc += bce_w(a1.w, b1.w, mid, t);
    }

    // warp reduction
    #pragma unroll
    for (int off = 16; off > 0; off >>= 1)
        acc += __shfl_xor_sync(0xFFFFFFFF, acc, off);

    __shared__ float warp_sums[8];
    const int lane = threadIdx.x & 31;
    const int wid  = threadIdx.x >> 5;
    if (lane == 0) warp_sums[wid] = acc;
    __syncthreads();

    if (wid == 0 && lane == 0) {
        float v = 0.0f;
        #pragma unroll
        for (int w = 0; w < 8; w++) v += warp_sums[w];

        atomicAdd(&g_accum, v);
        __threadfence();
        unsigned prev = atomicAdd(&g_done_count, 1u);
        if (prev == gridDim.x - 1) {
            // all blocks' g_accum adds are visible (each fenced before counter)
            out[0] = g_accum * inv_n;
            g_accum = 0.0f;        // reset for next graph replay
            g_done_count = 0;
        }
    }
}

extern "C" void kernel_launch(void* const* d_in, const int* in_sizes, int n_in,
                              void* d_out, int out_size) {
    const float* x      = (const float*)d_in[0];   // logits, N fp32
    const int*   target = (const int*)d_in[1];     // scalar int
    const int*   hidx   = (const int*)d_in[2];     // height_indices, N int32
    const int*   Hp     = (const int*)d_in[3];     // scalar int
    float* out = (float*)d_out;

    const int n = in_sizes[0];
    const int nvec8 = n / 8;   // N divisible by 8
    const float inv_n = 1.0f / (float)n;

    const int threads = 256;
    const int blocks  = 888;  // 148 SMs * 6
    rw_loss_kernel<<<blocks, threads>>>(
        (const float4*)x, (const int4*)hidx, target, Hp, out, nvec8, inv_n);
}